// round 1
// baseline (speedup 1.0000x reference)
#include <cuda_runtime.h>
#include <math.h>

#define NTOK 4096      // BATCH * SEQ
#define SEQ  2048
#define DEMB 1024
#define DFF  4096
#define NH   16
#define DH   64

// ---------------------------------------------------------------------------
// Scratch (static __device__ arrays; no allocation anywhere)
// ---------------------------------------------------------------------------
__device__ float g_ln [NTOK * DEMB];   // LN1 output, later reused for LN2
__device__ float g_q  [NTOK * DEMB];
__device__ float g_k  [NTOK * DEMB];
__device__ float g_v  [NTOK * DEMB];
__device__ float g_ctx[NTOK * DEMB];
__device__ float g_h  [NTOK * DEMB];   // residual after attention
__device__ float g_ff [NTOK * DFF];    // MLP hidden

// ---------------------------------------------------------------------------
// LayerNorm: one block per row, 256 threads
// ---------------------------------------------------------------------------
__global__ void __launch_bounds__(256) ln_kernel(
    const float* __restrict__ x, const float* __restrict__ sc,
    const float* __restrict__ sh, float* __restrict__ y)
{
    int row = blockIdx.x;
    const float* xr = x + (size_t)row * DEMB;
    float* yr = y + (size_t)row * DEMB;

    float sum = 0.f, sq = 0.f;
    for (int i = threadIdx.x; i < DEMB; i += 256) {
        float v = xr[i];
        sum += v; sq += v * v;
    }
    // warp reduce
    for (int o = 16; o > 0; o >>= 1) {
        sum += __shfl_down_sync(0xffffffffu, sum, o);
        sq  += __shfl_down_sync(0xffffffffu, sq,  o);
    }
    __shared__ float rs[8], rq[8];
    int wid = threadIdx.x >> 5, lane = threadIdx.x & 31;
    if (lane == 0) { rs[wid] = sum; rq[wid] = sq; }
    __syncthreads();
    __shared__ float s_mean, s_inv;
    if (wid == 0) {
        float a = (lane < 8) ? rs[lane] : 0.f;
        float b = (lane < 8) ? rq[lane] : 0.f;
        for (int o = 4; o > 0; o >>= 1) {
            a += __shfl_down_sync(0xffffffffu, a, o);
            b += __shfl_down_sync(0xffffffffu, b, o);
        }
        if (lane == 0) {
            float mean = a * (1.f / DEMB);
            float var  = b * (1.f / DEMB) - mean * mean;
            s_mean = mean;
            s_inv  = rsqrtf(var + 1e-6f);
        }
    }
    __syncthreads();
    float mean = s_mean, inv = s_inv;
    for (int i = threadIdx.x; i < DEMB; i += 256) {
        yr[i] = sc[i] * (xr[i] - mean) * inv + sh[i];
    }
}

// ---------------------------------------------------------------------------
// GEMM: C[M,N] = A[M,K] @ W[N,K]^T (+bias)(+residual)(GELU)
// 128x128 tile, BK=8, 256 threads, 8x8 per thread
// ---------------------------------------------------------------------------
__device__ __forceinline__ float gelu_tanh(float u) {
    return 0.5f * u * (1.f + tanhf(0.7978845608028654f * (u + 0.044715f * u * u * u)));
}

template<int BIAS, int GELU, int RES>
__global__ void __launch_bounds__(256) gemm_nt(
    const float* __restrict__ A, const float* __restrict__ W,
    const float* __restrict__ bias, const float* __restrict__ res,
    float* __restrict__ C, int M, int N, int K)
{
    __shared__ float As[8][128];
    __shared__ float Bs[8][128];

    int tid  = threadIdx.x;
    int row0 = blockIdx.y * 128;
    int col0 = blockIdx.x * 128;

    int lr = tid >> 1;          // 0..127
    int lk = (tid & 1) * 4;     // 0 or 4

    const float* Ag = A + (size_t)(row0 + lr) * K + lk;
    const float* Wg = W + (size_t)(col0 + lr) * K + lk;

    int tx = tid & 15, ty = tid >> 4;
    float acc[8][8];
#pragma unroll
    for (int i = 0; i < 8; i++)
#pragma unroll
        for (int j = 0; j < 8; j++) acc[i][j] = 0.f;

    for (int k0 = 0; k0 < K; k0 += 8) {
        float4 a = *(const float4*)(Ag + k0);
        float4 w = *(const float4*)(Wg + k0);
        __syncthreads();
        As[lk + 0][lr] = a.x; As[lk + 1][lr] = a.y;
        As[lk + 2][lr] = a.z; As[lk + 3][lr] = a.w;
        Bs[lk + 0][lr] = w.x; Bs[lk + 1][lr] = w.y;
        Bs[lk + 2][lr] = w.z; Bs[lk + 3][lr] = w.w;
        __syncthreads();
#pragma unroll
        for (int kk = 0; kk < 8; kk++) {
            float af[8], bf[8];
            *(float4*)&af[0] = *(const float4*)&As[kk][ty * 8];
            *(float4*)&af[4] = *(const float4*)&As[kk][ty * 8 + 4];
            *(float4*)&bf[0] = *(const float4*)&Bs[kk][tx * 8];
            *(float4*)&bf[4] = *(const float4*)&Bs[kk][tx * 8 + 4];
#pragma unroll
            for (int i = 0; i < 8; i++)
#pragma unroll
                for (int j = 0; j < 8; j++)
                    acc[i][j] += af[i] * bf[j];
        }
    }

#pragma unroll
    for (int i = 0; i < 8; i++) {
        int r = row0 + ty * 8 + i;
#pragma unroll
        for (int j = 0; j < 8; j++) {
            int c = col0 + tx * 8 + j;
            float v = acc[i][j];
            if (BIAS) v += bias[c];
            if (RES)  v += res[(size_t)r * N + c];
            if (GELU) v = gelu_tanh(v);
            C[(size_t)r * N + c] = v;
        }
    }
}

// ---------------------------------------------------------------------------
// Causal flash attention: one thread per query row.
// Block: 128 threads = 128 query rows; K/V tiles of 64 keys in smem.
// Grid: (SEQ/128, BATCH*NH)
// ---------------------------------------------------------------------------
__global__ void __launch_bounds__(128) attn_kernel()
{
    int bh = blockIdx.y;
    int b  = bh >> 4;
    int h  = bh & 15;
    int q0 = blockIdx.x * 128;
    int sq = q0 + threadIdx.x;          // query position within sequence
    int tok = b * SEQ + sq;

    const float4* Q4 = (const float4*)g_q;
    const float4* K4 = (const float4*)g_k;
    const float4* V4 = (const float4*)g_v;
    float4*       C4 = (float4*)g_ctx;

    int base = tok * (DEMB / 4) + h * (DH / 4);   // 16 float4 per head-row

    float4 q[16];
#pragma unroll
    for (int c = 0; c < 16; c++) q[c] = Q4[base + c];

    float4 acc[16];
#pragma unroll
    for (int c = 0; c < 16; c++) acc[c] = make_float4(0.f, 0.f, 0.f, 0.f);

    float m = -1e30f, l = 0.f;

    __shared__ float4 Ks[64][16];
    __shared__ float4 Vs[64][16];

    int ktmax = (q0 + 127) >> 6;   // inclusive last 64-key tile
    for (int kt = 0; kt <= ktmax; kt++) {
        __syncthreads();
        for (int idx = threadIdx.x; idx < 64 * 16; idx += 128) {
            int r = idx >> 4, c = idx & 15;
            int ktok = b * SEQ + kt * 64 + r;
            int kb = ktok * (DEMB / 4) + h * (DH / 4) + c;
            Ks[r][c] = K4[kb];
            Vs[r][c] = V4[kb];
        }
        __syncthreads();

        int jmax = sq - kt * 64 + 1;
        if (jmax > 64) jmax = 64;
        for (int j = 0; j < jmax; j++) {
            float s = 0.f;
#pragma unroll
            for (int c = 0; c < 16; c++) {
                float4 k4 = Ks[j][c];
                s += q[c].x * k4.x + q[c].y * k4.y
                   + q[c].z * k4.z + q[c].w * k4.w;
            }
            s *= 0.125f;   // 1/sqrt(64)
            if (s > m) {
                float corr = __expf(m - s);
                l *= corr;
#pragma unroll
                for (int c = 0; c < 16; c++) {
                    acc[c].x *= corr; acc[c].y *= corr;
                    acc[c].z *= corr; acc[c].w *= corr;
                }
                m = s;
            }
            float p = __expf(s - m);
            l += p;
#pragma unroll
            for (int c = 0; c < 16; c++) {
                float4 v4 = Vs[j][c];
                acc[c].x += p * v4.x; acc[c].y += p * v4.y;
                acc[c].z += p * v4.z; acc[c].w += p * v4.w;
            }
        }
    }

    float inv = 1.f / l;
#pragma unroll
    for (int c = 0; c < 16; c++) {
        C4[base + c] = make_float4(acc[c].x * inv, acc[c].y * inv,
                                   acc[c].z * inv, acc[c].w * inv);
    }
}

// ---------------------------------------------------------------------------
// Launch
// ---------------------------------------------------------------------------
extern "C" void kernel_launch(void* const* d_in, const int* in_sizes, int n_in,
                              void* d_out, int out_size)
{
    const float* x     = (const float*)d_in[0];
    const float* wq    = (const float*)d_in[1];
    const float* wk    = (const float*)d_in[2];
    const float* wv    = (const float*)d_in[3];
    const float* wo    = (const float*)d_in[4];
    const float* bo    = (const float*)d_in[5];
    const float* w1    = (const float*)d_in[6];
    const float* b1    = (const float*)d_in[7];
    const float* w2    = (const float*)d_in[8];
    const float* b2    = (const float*)d_in[9];
    const float* ln1_s = (const float*)d_in[10];
    const float* ln1_b = (const float*)d_in[11];
    const float* ln2_s = (const float*)d_in[12];
    const float* ln2_b = (const float*)d_in[13];
    float* out = (float*)d_out;

    float *p_ln, *p_q, *p_k, *p_v, *p_ctx, *p_h, *p_ff;
    cudaGetSymbolAddress((void**)&p_ln,  g_ln);
    cudaGetSymbolAddress((void**)&p_q,   g_q);
    cudaGetSymbolAddress((void**)&p_k,   g_k);
    cudaGetSymbolAddress((void**)&p_v,   g_v);
    cudaGetSymbolAddress((void**)&p_ctx, g_ctx);
    cudaGetSymbolAddress((void**)&p_h,   g_h);
    cudaGetSymbolAddress((void**)&p_ff,  g_ff);

    dim3 gD(DEMB / 128, NTOK / 128);   // N=1024 outputs
    dim3 gF(DFF  / 128, NTOK / 128);   // N=4096 outputs

    // LN1
    ln_kernel<<<NTOK, 256>>>(x, ln1_s, ln1_b, p_ln);
    // Q, K, V projections (no bias)
    gemm_nt<0, 0, 0><<<gD, 256>>>(p_ln, wq, nullptr, nullptr, p_q,  NTOK, DEMB, DEMB);
    gemm_nt<0, 0, 0><<<gD, 256>>>(p_ln, wk, nullptr, nullptr, p_k,  NTOK, DEMB, DEMB);
    gemm_nt<0, 0, 0><<<gD, 256>>>(p_ln, wv, nullptr, nullptr, p_v,  NTOK, DEMB, DEMB);
    // Causal attention
    attn_kernel<<<dim3(SEQ / 128, 2 * NH), 128>>>();
    // h = x + ctx @ wo^T + bo
    gemm_nt<1, 0, 1><<<gD, 256>>>(p_ctx, wo, bo, x, p_h, NTOK, DEMB, DEMB);
    // LN2 (reuse g_ln)
    ln_kernel<<<NTOK, 256>>>(p_h, ln2_s, ln2_b, p_ln);
    // ff = gelu(ln2 @ w1^T + b1)
    gemm_nt<1, 1, 0><<<gF, 256>>>(p_ln, w1, b1, nullptr, p_ff, NTOK, DFF, DEMB);
    // out = h + ff @ w2^T + b2
    gemm_nt<1, 0, 1><<<gD, 256>>>(p_ff, w2, b2, p_h, out, NTOK, DEMB, DFF);
}

// round 2
// speedup vs baseline: 1.9619x; 1.9619x over previous
#include <cuda_runtime.h>
#include <math.h>
#include <stdint.h>

#define NTOK 4096      // BATCH * SEQ
#define SEQ  2048
#define DEMB 1024
#define DFF  4096
#define NH   16
#define DH   64

// ---------------------------------------------------------------------------
// Scratch (static __device__ arrays; no allocation anywhere)
// ---------------------------------------------------------------------------
__device__ float g_ln [NTOK * DEMB];
__device__ float g_q  [NTOK * DEMB];
__device__ float g_k  [NTOK * DEMB];
__device__ float g_v  [NTOK * DEMB];
__device__ float g_ctx[NTOK * DEMB];
__device__ float g_h  [NTOK * DEMB];
__device__ float g_ff [NTOK * DFF];

// ---------------------------------------------------------------------------
// LayerNorm
// ---------------------------------------------------------------------------
__global__ void __launch_bounds__(256) ln_kernel(
    const float* __restrict__ x, const float* __restrict__ sc,
    const float* __restrict__ sh, float* __restrict__ y)
{
    int row = blockIdx.x;
    const float* xr = x + (size_t)row * DEMB;
    float* yr = y + (size_t)row * DEMB;

    float sum = 0.f, sq = 0.f;
    for (int i = threadIdx.x; i < DEMB; i += 256) {
        float v = xr[i];
        sum += v; sq += v * v;
    }
    for (int o = 16; o > 0; o >>= 1) {
        sum += __shfl_down_sync(0xffffffffu, sum, o);
        sq  += __shfl_down_sync(0xffffffffu, sq,  o);
    }
    __shared__ float rs[8], rq[8];
    int wid = threadIdx.x >> 5, lane = threadIdx.x & 31;
    if (lane == 0) { rs[wid] = sum; rq[wid] = sq; }
    __syncthreads();
    __shared__ float s_mean, s_inv;
    if (wid == 0) {
        float a = (lane < 8) ? rs[lane] : 0.f;
        float b = (lane < 8) ? rq[lane] : 0.f;
        for (int o = 4; o > 0; o >>= 1) {
            a += __shfl_down_sync(0xffffffffu, a, o);
            b += __shfl_down_sync(0xffffffffu, b, o);
        }
        if (lane == 0) {
            float mean = a * (1.f / DEMB);
            float var  = b * (1.f / DEMB) - mean * mean;
            s_mean = mean;
            s_inv  = rsqrtf(var + 1e-6f);
        }
    }
    __syncthreads();
    float mean = s_mean, inv = s_inv;
    for (int i = threadIdx.x; i < DEMB; i += 256) {
        yr[i] = sc[i] * (xr[i] - mean) * inv + sh[i];
    }
}

// ---------------------------------------------------------------------------
// TF32 tensor-core GEMM: C[M,N] = A[M,K] @ W[N,K]^T (+bias)(+res)(GELU)
// 128x128 block tile, BK=16, double-buffered smem, 8 warps (2x4), 64x32/warp
// ---------------------------------------------------------------------------
__device__ __forceinline__ float gelu_tanh(float u) {
    return 0.5f * u * (1.f + tanhf(0.7978845608028654f * (u + 0.044715f * u * u * u)));
}

__device__ __forceinline__ uint32_t f2tf(float f) {
    uint32_t u;
    asm("cvt.rna.tf32.f32 %0, %1;" : "=r"(u) : "f"(f));
    return u;
}

__device__ __forceinline__ void mma_tf32(float c[4],
    uint32_t a0, uint32_t a1, uint32_t a2, uint32_t a3,
    uint32_t b0, uint32_t b1)
{
    asm volatile(
        "mma.sync.aligned.m16n8k8.row.col.f32.tf32.tf32.f32 "
        "{%0,%1,%2,%3}, {%4,%5,%6,%7}, {%8,%9}, {%0,%1,%2,%3};\n"
        : "+f"(c[0]), "+f"(c[1]), "+f"(c[2]), "+f"(c[3])
        : "r"(a0), "r"(a1), "r"(a2), "r"(a3), "r"(b0), "r"(b1));
}

#define SPAD 20   // smem row stride in words (16 data + 4 pad)

template<int BIAS, int GELU, int RES>
__global__ void __launch_bounds__(256) gemm_tf32(
    const float* __restrict__ A, const float* __restrict__ W,
    const float* __restrict__ bias, const float* __restrict__ res,
    float* __restrict__ C, int M, int N, int K)
{
    __shared__ uint32_t sA[2][128 * SPAD];
    __shared__ uint32_t sB[2][128 * SPAD];

    int tid = threadIdx.x;
    int m0 = blockIdx.y * 128;
    int n0 = blockIdx.x * 128;

    // global load mapping: 256 threads cover 128x16 tile in two row-halves
    int lr = tid >> 2;             // 0..63
    int lc = (tid & 3) * 4;        // 0,4,8,12
    const float* Ag0 = A + (size_t)(m0 + lr)      * K + lc;
    const float* Ag1 = A + (size_t)(m0 + lr + 64) * K + lc;
    const float* Wg0 = W + (size_t)(n0 + lr)      * K + lc;
    const float* Wg1 = W + (size_t)(n0 + lr + 64) * K + lc;

    int warp = tid >> 5, lane = tid & 31;
    int wm = (warp >> 2) * 64;     // warp M offset (0,64)
    int wn = (warp & 3) * 32;      // warp N offset (0,32,64,96)
    int g = lane >> 2, t = lane & 3;

    float acc[4][4][4];
#pragma unroll
    for (int i = 0; i < 4; i++)
#pragma unroll
        for (int j = 0; j < 4; j++)
#pragma unroll
            for (int c = 0; c < 4; c++) acc[i][j][c] = 0.f;

    float4 ra0, ra1, rb0, rb1;

    // prologue: load k0=0 tile
    ra0 = *(const float4*)(Ag0);
    ra1 = *(const float4*)(Ag1);
    rb0 = *(const float4*)(Wg0);
    rb1 = *(const float4*)(Wg1);
    {
        uint4 u;
        u.x = f2tf(ra0.x); u.y = f2tf(ra0.y); u.z = f2tf(ra0.z); u.w = f2tf(ra0.w);
        *(uint4*)&sA[0][lr * SPAD + lc] = u;
        u.x = f2tf(ra1.x); u.y = f2tf(ra1.y); u.z = f2tf(ra1.z); u.w = f2tf(ra1.w);
        *(uint4*)&sA[0][(lr + 64) * SPAD + lc] = u;
        u.x = f2tf(rb0.x); u.y = f2tf(rb0.y); u.z = f2tf(rb0.z); u.w = f2tf(rb0.w);
        *(uint4*)&sB[0][lr * SPAD + lc] = u;
        u.x = f2tf(rb1.x); u.y = f2tf(rb1.y); u.z = f2tf(rb1.z); u.w = f2tf(rb1.w);
        *(uint4*)&sB[0][(lr + 64) * SPAD + lc] = u;
    }
    __syncthreads();

    int buf = 0;
    for (int k0 = 16; k0 <= K; k0 += 16) {
        bool more = (k0 < K);
        if (more) {
            ra0 = *(const float4*)(Ag0 + k0);
            ra1 = *(const float4*)(Ag1 + k0);
            rb0 = *(const float4*)(Wg0 + k0);
            rb1 = *(const float4*)(Wg1 + k0);
        }

        // compute on current buffer
        const uint32_t* As = sA[buf];
        const uint32_t* Bs = sB[buf];
#pragma unroll
        for (int ks = 0; ks < 16; ks += 8) {
            uint32_t af[4][4], bfr[4][2];
#pragma unroll
            for (int mt = 0; mt < 4; mt++) {
                const uint32_t* p = &As[(wm + mt * 16 + g) * SPAD + ks + t];
                af[mt][0] = p[0];
                af[mt][1] = p[8 * SPAD];
                af[mt][2] = p[4];
                af[mt][3] = p[8 * SPAD + 4];
            }
#pragma unroll
            for (int nt = 0; nt < 4; nt++) {
                const uint32_t* p = &Bs[(wn + nt * 8 + g) * SPAD + ks + t];
                bfr[nt][0] = p[0];
                bfr[nt][1] = p[4];
            }
#pragma unroll
            for (int mt = 0; mt < 4; mt++)
#pragma unroll
                for (int nt = 0; nt < 4; nt++)
                    mma_tf32(acc[mt][nt],
                             af[mt][0], af[mt][1], af[mt][2], af[mt][3],
                             bfr[nt][0], bfr[nt][1]);
        }

        if (more) {
            int nb = buf ^ 1;
            uint4 u;
            u.x = f2tf(ra0.x); u.y = f2tf(ra0.y); u.z = f2tf(ra0.z); u.w = f2tf(ra0.w);
            *(uint4*)&sA[nb][lr * SPAD + lc] = u;
            u.x = f2tf(ra1.x); u.y = f2tf(ra1.y); u.z = f2tf(ra1.z); u.w = f2tf(ra1.w);
            *(uint4*)&sA[nb][(lr + 64) * SPAD + lc] = u;
            u.x = f2tf(rb0.x); u.y = f2tf(rb0.y); u.z = f2tf(rb0.z); u.w = f2tf(rb0.w);
            *(uint4*)&sB[nb][lr * SPAD + lc] = u;
            u.x = f2tf(rb1.x); u.y = f2tf(rb1.y); u.z = f2tf(rb1.z); u.w = f2tf(rb1.w);
            *(uint4*)&sB[nb][(lr + 64) * SPAD + lc] = u;
            __syncthreads();
            buf = nb;
        }
    }

    // epilogue: c0=(g,2t) c1=(g,2t+1) c2=(g+8,2t) c3=(g+8,2t+1)
#pragma unroll
    for (int mt = 0; mt < 4; mt++) {
        int r = m0 + wm + mt * 16 + g;
#pragma unroll
        for (int nt = 0; nt < 4; nt++) {
            int cc = n0 + wn + nt * 8 + 2 * t;
            float v0 = acc[mt][nt][0], v1 = acc[mt][nt][1];
            float v2 = acc[mt][nt][2], v3 = acc[mt][nt][3];
            if (BIAS) {
                float b0 = bias[cc], b1 = bias[cc + 1];
                v0 += b0; v1 += b1; v2 += b0; v3 += b1;
            }
            if (RES) {
                const float* rp0 = res + (size_t)r * N + cc;
                const float* rp1 = res + (size_t)(r + 8) * N + cc;
                v0 += rp0[0]; v1 += rp0[1];
                v2 += rp1[0]; v3 += rp1[1];
            }
            if (GELU) {
                v0 = gelu_tanh(v0); v1 = gelu_tanh(v1);
                v2 = gelu_tanh(v2); v3 = gelu_tanh(v3);
            }
            *(float2*)(C + (size_t)r * N + cc)       = make_float2(v0, v1);
            *(float2*)(C + (size_t)(r + 8) * N + cc) = make_float2(v2, v3);
        }
    }
}

// ---------------------------------------------------------------------------
// Causal flash attention: one thread per query row (unchanged from R1)
// ---------------------------------------------------------------------------
__global__ void __launch_bounds__(128) attn_kernel()
{
    int bh = blockIdx.y;
    int b  = bh >> 4;
    int h  = bh & 15;
    int q0 = blockIdx.x * 128;
    int sq = q0 + threadIdx.x;
    int tok = b * SEQ + sq;

    const float4* Q4 = (const float4*)g_q;
    const float4* K4 = (const float4*)g_k;
    const float4* V4 = (const float4*)g_v;
    float4*       C4 = (float4*)g_ctx;

    int base = tok * (DEMB / 4) + h * (DH / 4);

    float4 q[16];
#pragma unroll
    for (int c = 0; c < 16; c++) q[c] = Q4[base + c];

    float4 acc[16];
#pragma unroll
    for (int c = 0; c < 16; c++) acc[c] = make_float4(0.f, 0.f, 0.f, 0.f);

    float m = -1e30f, l = 0.f;

    __shared__ float4 Ks[64][16];
    __shared__ float4 Vs[64][16];

    int ktmax = (q0 + 127) >> 6;
    for (int kt = 0; kt <= ktmax; kt++) {
        __syncthreads();
        for (int idx = threadIdx.x; idx < 64 * 16; idx += 128) {
            int r = idx >> 4, c = idx & 15;
            int ktok = b * SEQ + kt * 64 + r;
            int kb = ktok * (DEMB / 4) + h * (DH / 4) + c;
            Ks[r][c] = K4[kb];
            Vs[r][c] = V4[kb];
        }
        __syncthreads();

        int jmax = sq - kt * 64 + 1;
        if (jmax > 64) jmax = 64;
        for (int j = 0; j < jmax; j++) {
            float s = 0.f;
#pragma unroll
            for (int c = 0; c < 16; c++) {
                float4 k4 = Ks[j][c];
                s += q[c].x * k4.x + q[c].y * k4.y
                   + q[c].z * k4.z + q[c].w * k4.w;
            }
            s *= 0.125f;
            if (s > m) {
                float corr = __expf(m - s);
                l *= corr;
#pragma unroll
                for (int c = 0; c < 16; c++) {
                    acc[c].x *= corr; acc[c].y *= corr;
                    acc[c].z *= corr; acc[c].w *= corr;
                }
                m = s;
            }
            float p = __expf(s - m);
            l += p;
#pragma unroll
            for (int c = 0; c < 16; c++) {
                float4 v4 = Vs[j][c];
                acc[c].x += p * v4.x; acc[c].y += p * v4.y;
                acc[c].z += p * v4.z; acc[c].w += p * v4.w;
            }
        }
    }

    float inv = 1.f / l;
#pragma unroll
    for (int c = 0; c < 16; c++) {
        C4[base + c] = make_float4(acc[c].x * inv, acc[c].y * inv,
                                   acc[c].z * inv, acc[c].w * inv);
    }
}

// ---------------------------------------------------------------------------
// Launch
// ---------------------------------------------------------------------------
extern "C" void kernel_launch(void* const* d_in, const int* in_sizes, int n_in,
                              void* d_out, int out_size)
{
    const float* x     = (const float*)d_in[0];
    const float* wq    = (const float*)d_in[1];
    const float* wk    = (const float*)d_in[2];
    const float* wv    = (const float*)d_in[3];
    const float* wo    = (const float*)d_in[4];
    const float* bo    = (const float*)d_in[5];
    const float* w1    = (const float*)d_in[6];
    const float* b1    = (const float*)d_in[7];
    const float* w2    = (const float*)d_in[8];
    const float* b2    = (const float*)d_in[9];
    const float* ln1_s = (const float*)d_in[10];
    const float* ln1_b = (const float*)d_in[11];
    const float* ln2_s = (const float*)d_in[12];
    const float* ln2_b = (const float*)d_in[13];
    float* out = (float*)d_out;

    float *p_ln, *p_q, *p_k, *p_v, *p_ctx, *p_h, *p_ff;
    cudaGetSymbolAddress((void**)&p_ln,  g_ln);
    cudaGetSymbolAddress((void**)&p_q,   g_q);
    cudaGetSymbolAddress((void**)&p_k,   g_k);
    cudaGetSymbolAddress((void**)&p_v,   g_v);
    cudaGetSymbolAddress((void**)&p_ctx, g_ctx);
    cudaGetSymbolAddress((void**)&p_h,   g_h);
    cudaGetSymbolAddress((void**)&p_ff,  g_ff);

    dim3 gD(DEMB / 128, NTOK / 128);
    dim3 gF(DFF  / 128, NTOK / 128);

    ln_kernel<<<NTOK, 256>>>(x, ln1_s, ln1_b, p_ln);
    gemm_tf32<0, 0, 0><<<gD, 256>>>(p_ln, wq, nullptr, nullptr, p_q, NTOK, DEMB, DEMB);
    gemm_tf32<0, 0, 0><<<gD, 256>>>(p_ln, wk, nullptr, nullptr, p_k, NTOK, DEMB, DEMB);
    gemm_tf32<0, 0, 0><<<gD, 256>>>(p_ln, wv, nullptr, nullptr, p_v, NTOK, DEMB, DEMB);
    attn_kernel<<<dim3(SEQ / 128, 2 * NH), 128>>>();
    gemm_tf32<1, 0, 1><<<gD, 256>>>(p_ctx, wo, bo, x, p_h, NTOK, DEMB, DEMB);
    ln_kernel<<<NTOK, 256>>>(p_h, ln2_s, ln2_b, p_ln);
    gemm_tf32<1, 1, 0><<<gF, 256>>>(p_ln, w1, b1, nullptr, p_ff, NTOK, DFF, DEMB);
    gemm_tf32<1, 0, 1><<<gD, 256>>>(p_ff, w2, b2, p_h, out, NTOK, DEMB, DFF);
}